// round 13
// baseline (speedup 1.0000x reference)
#include <cuda_runtime.h>
#include <cstdint>

// B=4096, D=1000, tiers: [0,50)x[475,1000), [475,525)x[950,1000), gt: n x [n,1000) * 2/D
#define D_DIM   1000
#define TSIZE   50
#define T0_S2   475
#define T1_S1   475
#define T1_S2   950
#define MAXREL  8
#define NT      256
#define GRID_C  1184              // 148 SMs x 8 resident CTAs

// compare-exchange: keep min if d, else max
#define CE(v, pv, d) (v) = (d) ? fminf((v), (pv)) : fmaxf((v), (pv))

__device__ __forceinline__ void cp_async16(uint32_t smem_addr, const void* gptr) {
    asm volatile("cp.async.cg.shared.global [%0], [%1], 16;" :: "r"(smem_addr), "l"(gptr));
}
__device__ __forceinline__ void cp_commit() {
    asm volatile("cp.async.commit_group;" ::: "memory");
}
__device__ __forceinline__ void cp_wait_all() {
    asm volatile("cp.async.wait_group 0;" ::: "memory");
}

// Sort 64 floats ascending across one warp; element ids: a=lane, b=lane+32.
__device__ __forceinline__ void bitonic64(float& a, float& b, int lane)
{
    #pragma unroll
    for (int k = 2; k <= 16; k <<= 1) {
        #pragma unroll
        for (int j = k >> 1; j > 0; j >>= 1) {
            const bool d = ((lane & k) == 0) == ((lane & j) == 0);
            float pa = __shfl_xor_sync(0xffffffffu, a, j);
            float pb = __shfl_xor_sync(0xffffffffu, b, j);
            CE(a, pa, d); CE(b, pb, d);
        }
    }
    #pragma unroll
    for (int j = 16; j > 0; j >>= 1) {         // k=32: a asc, b desc
        const bool d = ((lane & j) == 0);
        float pa = __shfl_xor_sync(0xffffffffu, a, j);
        float pb = __shfl_xor_sync(0xffffffffu, b, j);
        CE(a, pa, d); CE(b, pb, !d);
    }
    { float lo = fminf(a, b), hi = fmaxf(a, b); a = lo; b = hi; }   // k=64, j=32
    #pragma unroll
    for (int j = 16; j > 0; j >>= 1) {
        const bool d = ((lane & j) == 0);
        float pa = __shfl_xor_sync(0xffffffffu, a, j);
        float pb = __shfl_xor_sync(0xffffffffu, b, j);
        CE(a, pa, d); CE(b, pb, d);
    }
}

// Sort 8 floats ascending on lanes 0-7 (lanes >=8 hold +inf pads; j<8 never mixes).
__device__ __forceinline__ void bitonic8(float& v, int lane)
{
    #pragma unroll
    for (int k = 2; k <= 8; k <<= 1) {
        #pragma unroll
        for (int j = k >> 1; j > 0; j >>= 1) {
            const bool d = ((lane & k) == 0) == ((lane & j) == 0);
            float pv = __shfl_xor_sync(0xffffffffu, v, j);
            CE(v, pv, d);
        }
    }
}

// 6-level count query, top-3 levels in registers: k = #{srt_i > -v}; pre[k] + k*v
__device__ __forceinline__ float tree_query(float v,
                                            const float* __restrict__ s0,
                                            const float* __restrict__ p0,
                                            float r31, float r15, float r47,
                                            float r7, float r23, float r39, float r55)
{
    const float key = -v;
    const bool c1 = (r31 > key);
    int k = c1 ? 32 : 0;
    const float mB = c1 ? r47 : r15;
    const bool c2 = (mB > key);
    k += c2 ? 16 : 0;
    const float mC = c1 ? (c2 ? r55 : r39) : (c2 ? r23 : r7);
    k += (mC > key) ? 8 : 0;
    if (s0[k + 3] > key) k += 4;
    if (s0[k + 1] > key) k += 2;
    if (s0[k]     > key) k += 1;
    return p0[k] + (float)k * v;
}

__global__ __launch_bounds__(NT, 8)
void mt_persist_kernel(const float* __restrict__ scores,
                       const int*   __restrict__ labels,
                       float* __restrict__ out, float inv_B, int B)
{
    const int tid  = threadIdx.x;
    const int lane = tid & 31;
    const int wid  = tid >> 5;

    // Zero the poisoned output. Block 0 is resident in wave 1; this lands within
    // ~50 cycles of grid start. Every accumulate atomic happens AFTER a CTA's
    // full multi-row loop (thousands of cycles in), and replays are
    // stream-serialized, so the zero always precedes all adds.
    if (blockIdx.x == 0 && tid == 0) atomicExch(out, 0.0f);

    __shared__ float buf[2][D_DIM];          // double-buffered row
    __shared__ float srt[2][64];             // sorted-descending t = 1-s1, -1e30 pad
    __shared__ float pre[2][65];             // pre[g][k] = sum of first k
    __shared__ __align__(16) float sgS[8];   // GT sorted t (desc, -1e30 pad)
    __shared__ float preg[12];               // GT prefix sums [0..8]
    __shared__ int   n_sh;
    __shared__ float wsum[NT / 32];

    int row = blockIdx.x;
    const int stride = gridDim.x;

    // ---- prologue: prefetch first row + its labels ----------------------
    if (tid < D_DIM / 4)
        cp_async16((uint32_t)__cvta_generic_to_shared(&buf[0][tid * 4]),
                   scores + (size_t)row * D_DIM + tid * 4);
    cp_commit();
    int lab = -1;
    if (wid == 2 && lane < MAXREL)
        lab = labels[(size_t)row * D_DIM + lane];

    float A0 = 0.0f, A1 = 0.0f, AG = 0.0f;   // raw sums, scaled once at the end
    int cb = 0;

    while (row < B) {
        const int nrow = row + stride;

        cp_wait_all();                        // current row landed
        __syncthreads();                      // visible to all; prev reads done

        // ---- issue prefetch for next row into the other buffer ----------
        int lab_next = -1;
        if (nrow < B) {
            if (tid < D_DIM / 4)
                cp_async16((uint32_t)__cvta_generic_to_shared(&buf[cb ^ 1][tid * 4]),
                           scores + (size_t)nrow * D_DIM + tid * 4);
            if (wid == 2 && lane < MAXREL)
                lab_next = labels[(size_t)nrow * D_DIM + lane];
        }
        cp_commit();                          // (empty group if no next row)

        const float* s = buf[cb];

        // ---- sorts + scans (warps 0-2); warps 3-7 pass straight to bar ---
        if (wid < 2) {
            const int base = wid ? T1_S1 : 0;
            float a = s[base + lane];
            float b = (lane + 32 < TSIZE) ? s[base + lane + 32] : 1e30f;
            bitonic64(a, b, lane);
            const float ta = 1.0f - a, tb = 1.0f - b;   // desc t, pads -> -1e30
            srt[wid][lane]      = ta;
            srt[wid][lane + 32] = tb;
            float xa = ta;
            #pragma unroll
            for (int d = 1; d < 32; d <<= 1) {
                float y = __shfl_up_sync(0xffffffffu, xa, d);
                if (lane >= d) xa += y;
            }
            const float tot = __shfl_sync(0xffffffffu, xa, 31);
            float xb = tb;
            #pragma unroll
            for (int d = 1; d < 32; d <<= 1) {
                float y = __shfl_up_sync(0xffffffffu, xb, d);
                if (lane >= d) xb += y;
            }
            xb += tot;
            pre[wid][lane + 1]  = xa;
            pre[wid][lane + 33] = xb;
            if (lane == 0) pre[wid][0] = 0.0f;
        } else if (wid == 2) {
            const unsigned m = __ballot_sync(0xffffffffu, lab > -1);
            const int n = __popc(m);
            float key = (lane < n) ? s[lane] : 1e30f;
            bitonic8(key, lane);
            const float tv = 1.0f - key;
            float x = tv;
            #pragma unroll
            for (int d = 1; d < 8; d <<= 1) {
                float y = __shfl_up_sync(0xffffffffu, x, d);
                if (lane >= d) x += y;
            }
            if (lane < MAXREL) { sgS[lane] = tv; preg[lane + 1] = x; }
            if (lane == 0)     { preg[0] = 0.0f; n_sh = n; }
        }
        __syncthreads();

        const int n = n_sh;

        // ---- tier0: 525 queries over all 256 threads (2 each + 13 x3) ----
        {
            const float* s0 = srt[0];
            const float* p0 = pre[0];
            const float r31 = s0[31], r15 = s0[15], r47 = s0[47];
            const float r7 = s0[7], r23 = s0[23], r39 = s0[39], r55 = s0[55];
            A0 += tree_query(s[T0_S2 + tid],       s0, p0, r31, r15, r47, r7, r23, r39, r55);
            A0 += tree_query(s[T0_S2 + 256 + tid], s0, p0, r31, r15, r47, r7, r23, r39, r55);
            if (tid < 525 - 512)
                A0 += tree_query(s[T0_S2 + 512 + tid], s0, p0, r31, r15, r47, r7, r23, r39, r55);
        }

        // ---- tier1: 50 queries on threads 64..113 ------------------------
        if (tid >= 64 && tid < 64 + TSIZE) {
            const float v   = s[T1_S2 + (tid - 64)];
            const float key = -v;
            int k = 0;
            #pragma unroll
            for (int st = 32; st; st >>= 1)
                if (srt[1][k + st - 1] > key) k += st;
            A1 += pre[1][k] + (float)k * v;
        }

        // ---- GT: 4 queries/thread; register 8-tree (+t7 term for k==8) ---
        {
            const float4 gA = *(const float4*)sgS;        // t0..t3
            const float4 gB = *(const float4*)(sgS + 4);  // t4..t7
            float w[4];
            w[0] = (tid >= n) ? s[tid] : -1e30f;
            w[1] = s[tid + 256];
            w[2] = s[tid + 512];
            w[3] = (tid < D_DIM - 768) ? s[tid + 768] : -1e30f;
            #pragma unroll
            for (int q = 0; q < 4; q++) {
                const float key = -w[q];
                const bool c1 = (gA.w > key);
                int k = c1 ? 4 : 0;
                const float m2 = c1 ? gB.y : gA.y;
                const bool c2 = (m2 > key);
                k += c2 ? 2 : 0;
                const float mc = c1 ? (c2 ? gB.z : gB.x)
                                    : (c2 ? gA.z : gA.x);
                k += (mc > key) ? 1 : 0;
                k += (gB.w > key) ? 1 : 0;                // t7: k==8 case
                AG += preg[k] + (float)k * w[q];
            }
        }

        row = nrow;
        lab = lab_next;
        cb ^= 1;
    }

    // ---- epilogue: scale once, block reduce, one atomic per CTA ----------
    float loss = A0 * (1.0f / (TSIZE * 525.0f))
               + A1 * (1.0f / (TSIZE * (float)TSIZE))
               + AG * (2.0f / (float)D_DIM);

    #pragma unroll
    for (int off = 16; off > 0; off >>= 1)
        loss += __shfl_xor_sync(0xffffffffu, loss, off);
    if (lane == 0) wsum[wid] = loss;
    __syncthreads();
    if (tid == 0) {
        float t = 0.0f;
        #pragma unroll
        for (int w2 = 0; w2 < NT / 32; w2++) t += wsum[w2];
        atomicAdd(out, t * inv_B);
    }
}

extern "C" void kernel_launch(void* const* d_in, const int* in_sizes, int n_in,
                              void* d_out, int out_size)
{
    const float* scores = (const float*)d_in[0];
    const int*   labels = (const int*)d_in[1];
    float*       out    = (float*)d_out;

    const int B    = in_sizes[0] / D_DIM;
    const int grid = (B < GRID_C) ? B : GRID_C;

    mt_persist_kernel<<<grid, NT>>>(scores, labels, out, 1.0f / (float)B, B);
}

// round 14
// speedup vs baseline: 1.3674x; 1.3674x over previous
#include <cuda_runtime.h>

// B=4096, D=1000, tiers: [0,50)x[475,1000), [475,525)x[950,1000), gt: n x [n,1000) * 2/D
#define D_DIM   1000
#define TSIZE   50
#define T0_S2   475
#define T1_S1   475
#define T1_S2   950
#define MAXREL  8
#define NT      256

// compare-exchange: keep min if d, else max
#define CE(v, pv, d) (v) = (d) ? fminf((v), (pv)) : fmaxf((v), (pv))

// Sort 64 floats ascending across one warp; element ids: a=lane, b=lane+32.
__device__ __forceinline__ void bitonic64(float& a, float& b, int lane)
{
    #pragma unroll
    for (int k = 2; k <= 16; k <<= 1) {
        #pragma unroll
        for (int j = k >> 1; j > 0; j >>= 1) {
            const bool d = ((lane & k) == 0) == ((lane & j) == 0);
            float pa = __shfl_xor_sync(0xffffffffu, a, j);
            float pb = __shfl_xor_sync(0xffffffffu, b, j);
            CE(a, pa, d); CE(b, pb, d);
        }
    }
    #pragma unroll
    for (int j = 16; j > 0; j >>= 1) {         // k=32: a asc, b desc
        const bool d = ((lane & j) == 0);
        float pa = __shfl_xor_sync(0xffffffffu, a, j);
        float pb = __shfl_xor_sync(0xffffffffu, b, j);
        CE(a, pa, d); CE(b, pb, !d);
    }
    { float lo = fminf(a, b), hi = fmaxf(a, b); a = lo; b = hi; }   // k=64, j=32
    #pragma unroll
    for (int j = 16; j > 0; j >>= 1) {
        const bool d = ((lane & j) == 0);
        float pa = __shfl_xor_sync(0xffffffffu, a, j);
        float pb = __shfl_xor_sync(0xffffffffu, b, j);
        CE(a, pa, d); CE(b, pb, d);
    }
}

// Sort 8 floats ascending on lanes 0-7 (lanes >=8 hold +inf pads; j<8 never mixes).
__device__ __forceinline__ void bitonic8(float& v, int lane)
{
    #pragma unroll
    for (int k = 2; k <= 8; k <<= 1) {
        #pragma unroll
        for (int j = k >> 1; j > 0; j >>= 1) {
            const bool d = ((lane & k) == 0) == ((lane & j) == 0);
            float pv = __shfl_xor_sync(0xffffffffu, v, j);
            CE(v, pv, d);
        }
    }
}

// 6-level count query, top-3 levels in registers: k = #{srt_i > -v}; pre[k] + k*v
__device__ __forceinline__ float tree_query(float v,
                                            const float* __restrict__ s0,
                                            const float* __restrict__ p0,
                                            float r31, float r15, float r47,
                                            float r7, float r23, float r39, float r55)
{
    const float key = -v;
    const bool c1 = (r31 > key);
    int k = c1 ? 32 : 0;
    const float mB = c1 ? r47 : r15;
    const bool c2 = (mB > key);
    k += c2 ? 16 : 0;
    const float mC = c1 ? (c2 ? r55 : r39) : (c2 ? r23 : r7);
    k += (mC > key) ? 8 : 0;
    if (s0[k + 3] > key) k += 4;
    if (s0[k + 1] > key) k += 2;
    if (s0[k]     > key) k += 1;
    return p0[k] + (float)k * v;
}

__global__ __launch_bounds__(NT, 8)
void mt2_kernel(const float* __restrict__ scores,
                const int*   __restrict__ labels,
                float* __restrict__ out, float inv_B, int B)
{
    const int tid  = threadIdx.x;
    const int lane = tid & 31;
    const int wid  = tid >> 5;

    // Zero the poisoned output. Block 0 is resident in wave 1; this lands within
    // ~50 cycles of grid start; every accumulate atomic is >= ~2000 cycles into
    // its block's execution, and graph replays are stream-serialized.
    if (blockIdx.x == 0 && tid == 0) atomicExch(out, 0.0f);

    __shared__ float s[2][D_DIM];            // two rows side by side
    __shared__ float srt[2][2][64];          // [row][tier] sorted-desc t, -1e30 pad
    __shared__ float pre[2][2][65];          // [row][tier] prefix sums
    __shared__ __align__(16) float sgS[2][8];// [row] GT sorted t (desc, -1e30 pad)
    __shared__ float preg[2][12];            // [row] GT prefix sums [0..8]
    __shared__ int   n_sh[2];
    __shared__ float wsum[NT / 32];

    const int  rA     = blockIdx.x * 2;
    const bool bValid = (rA + 1 < B);
    const int  rB     = bValid ? rA + 1 : rA;     // clamp -> safe loads, zeroed later

    const float* srcA = scores + (size_t)rA * D_DIM;
    const float* srcB = scores + (size_t)rB * D_DIM;

    // ================= phase 1: all 8 warps busy =========================
    if (wid == 3 || wid == 7) {
        // load both rows: 500 float4 over 64 threads (8 iters, last partial)
        const int t64 = lane + ((wid == 7) ? 32 : 0);
        #pragma unroll
        for (int i = t64; i < 500; i += 64) {
            const int r = (i >= 250) ? 1 : 0;
            const int o = i - r * 250;
            ((float4*)s[r])[o] = ((const float4*)(r ? srcB : srcA))[o];
        }
    } else {
        const int rs   = wid >> 2;                // 0 for w0-2, 1 for w4-6
        const int wloc = wid & 3;                 // 0,1 = tier sorts, 2 = GT
        const float* src = rs ? srcB : srcA;
        if (wloc < 2) {
            const int base = wloc ? T1_S1 : 0;
            float a = src[base + lane];
            float b = (lane + 32 < TSIZE) ? src[base + lane + 32] : 1e30f;
            bitonic64(a, b, lane);
            const float ta = 1.0f - a, tb = 1.0f - b;   // desc t, pads -> -1e30
            srt[rs][wloc][lane]      = ta;
            srt[rs][wloc][lane + 32] = tb;
            float xa = ta;
            #pragma unroll
            for (int d = 1; d < 32; d <<= 1) {
                float y = __shfl_up_sync(0xffffffffu, xa, d);
                if (lane >= d) xa += y;
            }
            const float tot = __shfl_sync(0xffffffffu, xa, 31);
            float xb = tb;
            #pragma unroll
            for (int d = 1; d < 32; d <<= 1) {
                float y = __shfl_up_sync(0xffffffffu, xb, d);
                if (lane >= d) xb += y;
            }
            xb += tot;
            pre[rs][wloc][lane + 1]  = xa;
            pre[rs][wloc][lane + 33] = xb;
            if (lane == 0) pre[rs][wloc][0] = 0.0f;
        } else {
            // GT anchors for this row
            const int* lr = labels + (size_t)(rs ? rB : rA) * D_DIM;
            const int  lab = (lane < MAXREL) ? lr[lane] : -1;
            const unsigned m = __ballot_sync(0xffffffffu, lab > -1);
            const int n = __popc(m);
            float key = (lane < n) ? src[lane] : 1e30f;
            bitonic8(key, lane);
            const float tv = 1.0f - key;
            float x = tv;
            #pragma unroll
            for (int d = 1; d < 8; d <<= 1) {
                float y = __shfl_up_sync(0xffffffffu, x, d);
                if (lane >= d) x += y;
            }
            if (lane < MAXREL) { sgS[rs][lane] = tv; preg[rs][lane + 1] = x; }
            if (lane == 0)     { preg[rs][0] = 0.0f; n_sh[rs] = n; }
        }
    }
    __syncthreads();

    // ================= phase 2: half-block per row =======================
    const int   tl = tid & 127;               // thread-in-half
    const int   rs = tid >> 7;                // 0 = row A, 1 = row B
    const float fv = (rs == 0 || bValid) ? 1.0f : 0.0f;
    const float* sR = s[rs];
    const int    n  = n_sh[rs];

    float A0 = 0.0f, A1 = 0.0f, AG = 0.0f;

    // ---- tier0: 525 = 128*4 + 13 queries per row ------------------------
    {
        const float* s0 = srt[rs][0];
        const float* p0 = pre[rs][0];
        const float r31 = s0[31], r15 = s0[15], r47 = s0[47];
        const float r7 = s0[7], r23 = s0[23], r39 = s0[39], r55 = s0[55];
        #pragma unroll
        for (int q = 0; q < 4; q++)
            A0 += tree_query(sR[T0_S2 + tl + q * 128], s0, p0,
                             r31, r15, r47, r7, r23, r39, r55);
        if (tl < 525 - 512)
            A0 += tree_query(sR[T0_S2 + 512 + tl], s0, p0,
                             r31, r15, r47, r7, r23, r39, r55);
    }

    // ---- tier1: 50 queries on tl in [64,114) per row --------------------
    if (tl >= 64 && tl < 64 + TSIZE) {
        const float v   = sR[T1_S2 + (tl - 64)];
        const float key = -v;
        int k = 0;
        #pragma unroll
        for (int st = 32; st; st >>= 1)
            if (srt[rs][1][k + st - 1] > key) k += st;
        A1 = pre[rs][1][k] + (float)k * v;
    }

    // ---- GT: 8 queries/thread per row (k = tl + q*128) ------------------
    // 3-level register tree yields k in [0,7]; the extra (t7 > key) term is
    // exact: it fires iff all 8 anchors hold (tree says 7) -> k=8.
    {
        const float4 gA = *(const float4*)sgS[rs];        // t0..t3
        const float4 gB = *(const float4*)(sgS[rs] + 4);  // t4..t7
        const float* pg = preg[rs];
        #pragma unroll
        for (int q = 0; q < 8; q++) {
            const int kidx = tl + q * 128;
            float w;
            if (q == 0)      w = (kidx >= n)     ? sR[kidx] : -1e30f;
            else if (q == 7) w = (kidx < D_DIM)  ? sR[kidx] : -1e30f;
            else             w = sR[kidx];
            const float key = -w;
            const bool c1 = (gA.w > key);
            int k = c1 ? 4 : 0;
            const float m2 = c1 ? gB.y : gA.y;
            const bool c2 = (m2 > key);
            k += c2 ? 2 : 0;
            const float mc = c1 ? (c2 ? gB.z : gB.x)
                                : (c2 ? gA.z : gA.x);
            k += (mc > key) ? 1 : 0;
            k += (gB.w > key) ? 1 : 0;                    // t7: k==8 case
            AG += pg[k] + (float)k * w;
        }
    }

    float loss = (A0 * (1.0f / (TSIZE * 525.0f))
                + A1 * (1.0f / (TSIZE * (float)TSIZE))
                + AG * (2.0f / (float)D_DIM)) * fv;

    // ---- block reduce + single atomic (covers both rows) ----------------
    #pragma unroll
    for (int off = 16; off > 0; off >>= 1)
        loss += __shfl_xor_sync(0xffffffffu, loss, off);
    if (lane == 0) wsum[wid] = loss;
    __syncthreads();
    if (tid == 0) {
        float t = 0.0f;
        #pragma unroll
        for (int w2 = 0; w2 < NT / 32; w2++) t += wsum[w2];
        atomicAdd(out, t * inv_B);
    }
}

extern "C" void kernel_launch(void* const* d_in, const int* in_sizes, int n_in,
                              void* d_out, int out_size)
{
    const float* scores = (const float*)d_in[0];
    const int*   labels = (const int*)d_in[1];
    float*       out    = (float*)d_out;

    const int B    = in_sizes[0] / D_DIM;
    const int grid = (B + 1) / 2;

    mt2_kernel<<<grid, NT>>>(scores, labels, out, 1.0f / (float)B, B);
}